// round 7
// baseline (speedup 1.0000x reference)
#include <cuda_runtime.h>
#include <math.h>

#define TT   128
#define BB   512
#define HH   128
#define EMBD 300
#define DD   256
#define G3   384
#define EPSF 1e-7f

typedef long long ll;

__device__ float g_xp_f[TT * BB * G3];
__device__ float g_xp_b[TT * BB * G3];
__device__ float g_ys_f[TT * BB * HH];
__device__ float g_ys_b[TT * BB * HH];
__device__ float g_hyp[TT * BB * DD];
__device__ float g_scores[TT * BB];
__device__ float g_rr2[TT * BB];
__device__ float g_cc[2];   // [cosh(rc), sinh(rc)/rc]

// ---- tf32 helpers ----
__device__ __forceinline__ unsigned f2tf32(float v) {
    unsigned u;
    asm("cvt.rna.tf32.f32 %0, %1;" : "=r"(u) : "f"(v));
    return u;
}
__device__ __forceinline__ void mma_tf32(float* c, const unsigned* a, const unsigned* b) {
    asm volatile(
        "mma.sync.aligned.m16n8k8.row.col.f32.tf32.tf32.f32 "
        "{%0,%1,%2,%3}, {%4,%5,%6,%7}, {%8,%9}, {%0,%1,%2,%3};"
        : "+f"(c[0]), "+f"(c[1]), "+f"(c[2]), "+f"(c[3])
        : "r"(a[0]), "r"(a[1]), "r"(a[2]), "r"(a[3]), "r"(b[0]), "r"(b[1]));
}

#define ACH 1032
#define BCH 1032
#define MMA_SMEM ((8 * ACH + 8 * BCH) * 4)   // 66,048 B

__device__ __forceinline__ int a_off(int r, int kk) {
    return (kk >> 3) * ACH + (r >> 4) * 128 + ((((r & 7) << 2) | (kk & 3)) << 2)
           + ((r >> 3) & 1) + (((kk >> 2) & 1) << 1);
}
__device__ __forceinline__ int b_off(int c, int kk) {
    return (kk >> 3) * BCH + (c >> 3) * 64 + ((((c & 7) << 2) | (kk & 3)) << 1)
           + ((kk >> 2) & 1);
}

// ============================================================
// K0: centroid constants (1 block, 32 threads)
// ============================================================
__global__ void k0_cent(const float* __restrict__ cent)
{
    const int lane = threadIdx.x;
    float c2 = 0.f;
    #pragma unroll
    for (int i = 0; i < 8; i++) {
        const float cv = cent[lane + 32 * i];
        c2 += cv * cv;
    }
    #pragma unroll
    for (int o = 16; o; o >>= 1) c2 += __shfl_xor_sync(0xffffffffu, c2, o);
    if (lane == 0) {
        const float rc = sqrtf(c2);
        g_cc[0] = coshf(rc);
        g_cc[1] = sinhf(rc) / rc;
    }
}

// ============================================================
// K1: embed gather + input projections via tf32 mma.
// grid (6 colblocks, nRowBlocks) — colblocks consecutive => L2 reuse of A
// ============================================================
__global__ __launch_bounds__(256) void k1_mma(
    const int* __restrict__ tokens, const float* __restrict__ emb,
    const float* __restrict__ Wf, const float* __restrict__ bfv,
    const float* __restrict__ Wb, const float* __restrict__ bbv,
    int rb_off)
{
    extern __shared__ unsigned sm_u[];
    unsigned* As = sm_u;
    unsigned* Bs = sm_u + 8 * ACH;
    __shared__ int tk[128];

    const int tid  = threadIdx.x;
    const int lane = tid & 31;
    const int w    = tid >> 5;
    const int wm   = w >> 2;
    const int wn   = w & 3;
    const int row0 = (blockIdx.y + rb_off) * 128;
    const int t    = row0 >> 9;
    const int b0   = row0 & 511;
    const int coff = blockIdx.x * 128;

    if (tid < 128) tk[tid] = tokens[row0 + tid];

    const bool fwd = (coff < G3);
    const float* Wsrc = fwd ? Wf : Wb;
    const float* bsrc = fwd ? bfv : bbv;
    const int cbase = fwd ? coff : (coff - G3);

    float acc[4][4][4];
    #pragma unroll
    for (int i = 0; i < 4; i++)
        #pragma unroll
        for (int j = 0; j < 4; j++)
            #pragma unroll
            for (int q = 0; q < 4; q++) acc[i][j][q] = 0.f;

    const int kk = tid & 63;
    const int rg = tid >> 6;

    for (int ks = 0; ks < 5; ks++) {
        const int kg = ks * 64 + kk;
        const bool kv = (kg < EMBD);
        __syncthreads();
        #pragma unroll 4
        for (int r = rg; r < 128; r += 4) {
            float v = kv ? emb[(ll)tk[r] * EMBD + kg] : 0.f;
            As[a_off(r, kk)] = f2tf32(v);
        }
        #pragma unroll 4
        for (int c = rg; c < 128; c += 4) {
            float v = kv ? Wsrc[(ll)(cbase + c) * EMBD + kg] : 0.f;
            Bs[b_off(c, kk)] = f2tf32(v);
        }
        __syncthreads();
        #pragma unroll
        for (int ck = 0; ck < 8; ck++) {
            unsigned a[4][4], b[4][2];
            #pragma unroll
            for (int i = 0; i < 4; i++) {
                uint4 av = *(const uint4*)(As + ck * ACH + (wm * 4 + i) * 128 + lane * 4);
                a[i][0] = av.x; a[i][1] = av.y; a[i][2] = av.z; a[i][3] = av.w;
            }
            #pragma unroll
            for (int j = 0; j < 4; j++) {
                uint2 bv = *(const uint2*)(Bs + ck * BCH + (wn * 4 + j) * 64 + lane * 2);
                b[j][0] = bv.x; b[j][1] = bv.y;
            }
            #pragma unroll
            for (int i = 0; i < 4; i++)
                #pragma unroll
                for (int j = 0; j < 4; j++)
                    mma_tf32(acc[i][j], a[i], b[j]);
        }
    }

    const int tb = TT - 1 - t;
    #pragma unroll
    for (int j = 0; j < 4; j++) {
        const int cl = cbase + wn * 32 + j * 8 + 2 * (lane & 3);
        const float bv0 = bsrc[cl], bv1 = bsrc[cl + 1];
        #pragma unroll
        for (int i = 0; i < 4; i++) {
            const int b_lo = b0 + wm * 64 + i * 16 + (lane >> 2);
            float2 vlo = make_float2(acc[i][j][0] + bv0, acc[i][j][1] + bv1);
            float2 vhi = make_float2(acc[i][j][2] + bv0, acc[i][j][3] + bv1);
            if (fwd) {
                *(float2*)&g_xp_f[((ll)t * BB + b_lo) * G3 + cl] = vlo;
                *(float2*)&g_xp_f[((ll)t * BB + b_lo + 8) * G3 + cl] = vhi;
            } else {
                *(float2*)&g_xp_b[((ll)tb * BB + b_lo) * G3 + cl] = vlo;
                *(float2*)&g_xp_b[((ll)tb * BB + b_lo + 8) * G3 + cl] = vhi;
            }
        }
    }
}

// ============================================================
// K2: GRU scan (fp32). 128 blocks x 384 thr. (profiled this round)
// ============================================================
__global__ __launch_bounds__(384, 1) void k2_scan(
    const float* __restrict__ hidden,
    const float* __restrict__ Whh_f, const float* __restrict__ bhh_f,
    const float* __restrict__ Whh_b, const float* __restrict__ bhh_b)
{
    __shared__ __align__(16) float hs[8 * 128];
    __shared__ float sg[256 * 9];

    const int tid = threadIdx.x;
    const int dir = blockIdx.x >> 6;
    const int b0  = (blockIdx.x & 63) * 8;

    const float* Whh = dir ? Whh_b : Whh_f;
    const float* bhh = dir ? bhh_b : bhh_f;
    const float* xp  = dir ? g_xp_b : g_xp_f;
    float* ys        = dir ? g_ys_b : g_ys_f;

    float4 w[32];
    #pragma unroll
    for (int i = 0; i < 32; i++)
        w[i] = *(const float4*)&Whh[tid * 128 + i * 4];
    const float bj = bhh[tid];

    if (tid < 128) {
        #pragma unroll
        for (int r = 0; r < 8; r++)
            hs[r * 128 + tid] = hidden[((ll)dir * BB + b0 + r) * HH + tid];
    }
    __syncthreads();

    const float4* h4 = (const float4*)hs;

    for (int t = 0; t < TT; t++) {
        float xpv[8];
        const float* xpt = xp + ((ll)t * BB + b0) * G3 + tid;
        #pragma unroll
        for (int r = 0; r < 8; r++) xpv[r] = xpt[r * (ll)G3];

        float acc[8];
        #pragma unroll
        for (int r = 0; r < 8; r++) acc[r] = 0.f;

        #pragma unroll
        for (int i = 0; i < 32; i++) {
            const float4 wi = w[i];
            #pragma unroll
            for (int r = 0; r < 8; r++) {
                const float4 hv = h4[r * 32 + i];
                acc[r] += wi.x * hv.x + wi.y * hv.y + wi.z * hv.z + wi.w * hv.w;
            }
        }

        if (tid < 256) {
            #pragma unroll
            for (int r = 0; r < 8; r++) {
                const float x = xpv[r] + acc[r] + bj;
                sg[tid * 9 + r] = __fdividef(1.f, 1.f + __expf(-x));
            }
        }
        __syncthreads();
        if (tid >= 256) {
            const int k = tid - 256;
            float* ysrow = ys + ((ll)t * BB + b0) * HH + k;
            #pragma unroll
            for (int r = 0; r < 8; r++) {
                const float rg = sg[k * 9 + r];
                const float zg = sg[(128 + k) * 9 + r];
                const float a  = xpv[r] + rg * (acc[r] + bj);
                const float e  = __expf(2.f * a);
                const float n  = 1.f - __fdividef(2.f, e + 1.f);
                const float ho = hs[r * 128 + k];
                const float hnew = (1.f - zg) * n + zg * ho;
                hs[r * 128 + k] = hnew;
                ysrow[r * (ll)HH] = hnew;
            }
        }
        __syncthreads();
    }
}

// ============================================================
// K3: hyp = tanh(f @ attn2_W^T + b) via tf32 mma.
// grid (2 colblocks, 512 rowblocks)
// ============================================================
__global__ __launch_bounds__(256) void k3_mma(
    const float* __restrict__ W, const float* __restrict__ bias)
{
    extern __shared__ unsigned sm_u[];
    unsigned* As = sm_u;
    unsigned* Bs = sm_u + 8 * ACH;

    const int tid  = threadIdx.x;
    const int lane = tid & 31;
    const int w    = tid >> 5;
    const int wm   = w >> 2;
    const int wn   = w & 3;
    const int row0 = blockIdx.y * 128;
    const int t    = row0 >> 9;
    const int b0   = row0 & 511;
    const int tb   = TT - 1 - t;
    const int coff = blockIdx.x * 128;

    float acc[4][4][4];
    #pragma unroll
    for (int i = 0; i < 4; i++)
        #pragma unroll
        for (int j = 0; j < 4; j++)
            #pragma unroll
            for (int q = 0; q < 4; q++) acc[i][j][q] = 0.f;

    const int kk = tid & 63;
    const int rg = tid >> 6;

    for (int ks = 0; ks < 4; ks++) {
        const int kg = ks * 64 + kk;
        __syncthreads();
        #pragma unroll 4
        for (int r = rg; r < 128; r += 4) {
            const int b = b0 + r;
            float v = (kg < HH)
                ? g_ys_f[((ll)t * BB + b) * HH + kg]
                : g_ys_b[((ll)tb * BB + b) * HH + (kg - HH)];
            As[a_off(r, kk)] = f2tf32(v);
        }
        #pragma unroll 4
        for (int c = rg; c < 128; c += 4) {
            float v = W[(ll)(coff + c) * DD + kg];
            Bs[b_off(c, kk)] = f2tf32(v);
        }
        __syncthreads();
        #pragma unroll
        for (int ck = 0; ck < 8; ck++) {
            unsigned a[4][4], b[4][2];
            #pragma unroll
            for (int i = 0; i < 4; i++) {
                uint4 av = *(const uint4*)(As + ck * ACH + (wm * 4 + i) * 128 + lane * 4);
                a[i][0] = av.x; a[i][1] = av.y; a[i][2] = av.z; a[i][3] = av.w;
            }
            #pragma unroll
            for (int j = 0; j < 4; j++) {
                uint2 bv = *(const uint2*)(Bs + ck * BCH + (wn * 4 + j) * 64 + lane * 2);
                b[j][0] = bv.x; b[j][1] = bv.y;
            }
            #pragma unroll
            for (int i = 0; i < 4; i++)
                #pragma unroll
                for (int j = 0; j < 4; j++)
                    mma_tf32(acc[i][j], a[i], b[j]);
        }
    }

    #pragma unroll
    for (int j = 0; j < 4; j++) {
        const int n = coff + wn * 32 + j * 8 + 2 * (lane & 3);
        const float bv0 = bias[n], bv1 = bias[n + 1];
        #pragma unroll
        for (int i = 0; i < 4; i++) {
            const int m_lo = row0 + wm * 64 + i * 16 + (lane >> 2);
            float v[4] = {acc[i][j][0] + bv0, acc[i][j][1] + bv1,
                          acc[i][j][2] + bv0, acc[i][j][3] + bv1};
            #pragma unroll
            for (int q = 0; q < 4; q++) {
                const float e = __expf(2.f * v[q]);
                v[q] = 1.f - __fdividef(2.f, e + 1.f);
            }
            *(float2*)&g_hyp[(ll)m_lo * DD + n] = make_float2(v[0], v[1]);
            *(float2*)&g_hyp[(ll)(m_lo + 8) * DD + n] = make_float2(v[2], v[3]);
        }
    }
}

// ============================================================
// K34: fused ||f||^2 + hyperbolic score, one warp per (t,b) row
// ============================================================
__global__ __launch_bounds__(256) void k34_scores(
    const float* __restrict__ cent, const float* __restrict__ beta)
{
    const int row  = blockIdx.x * 8 + (threadIdx.x >> 5);
    const int lane = threadIdx.x & 31;
    const int t = row >> 9, b = row & 511;
    const float* yf = g_ys_f + ((ll)t * BB + b) * HH;
    const float* yb = g_ys_b + ((ll)(TT - 1 - t) * BB + b) * HH;
    const float* hy = g_hyp + (ll)row * DD;

    float s = 0.f, h2 = 0.f, cd = 0.f;
    #pragma unroll
    for (int i = 0; i < 4; i++) {
        const float a = yf[lane + 32 * i];
        const float c = yb[lane + 32 * i];
        s += a * a + c * c;
    }
    #pragma unroll
    for (int i = 0; i < 8; i++) {
        const float hv = hy[lane + 32 * i];
        const float cv = cent[lane + 32 * i];
        h2 += hv * hv; cd += hv * cv;
    }
    #pragma unroll
    for (int o = 16; o; o >>= 1) {
        s  += __shfl_xor_sync(0xffffffffu, s, o);
        h2 += __shfl_xor_sync(0xffffffffu, h2, o);
        cd += __shfl_xor_sync(0xffffffffu, cd, o);
    }
    if (lane == 0) {
        g_rr2[row] = s;
        const float rh = sqrtf(h2);
        float pm = coshf(rh) * g_cc[0] - (sinhf(rh) / rh) * g_cc[1] * cd;
        pm = fminf(fmaxf(pm, 1.f + EPSF), 1e16f);
        const float dist = logf(pm) + log1pf(sqrtf(pm * pm - 1.f + EPSF) / pm);
        g_scores[row] = -beta[0] * dist - 1.f;
    }
}

// ============================================================
// K5: softmax x gamma Einstein-midpoint pooling + h_output
// ============================================================
__global__ __launch_bounds__(256) void k5_pool(float* __restrict__ out)
{
    __shared__ float wk[128];
    __shared__ float red[128];
    const int b = blockIdx.x, tid = threadIdx.x;

    float s = -1e30f;
    if (tid < 128) {
        s = g_scores[tid * BB + b];
        red[tid] = s;
    }
    __syncthreads();
    for (int o = 64; o; o >>= 1) {
        if (tid < o) red[tid] = fmaxf(red[tid], red[tid + o]);
        __syncthreads();
    }
    const float smax = red[0];
    __syncthreads();

    float myw = 0.f, kf = 0.f;
    if (tid < 128) {
        const float rr = sqrtf(g_rr2[tid * BB + b]);
        const float sh = sinhf(rr), ch = coshf(rr);
        const float th = sh / ch;
        float gsq = 1.f - th * th;
        gsq = fminf(fmaxf(gsq, EPSF), 1.f - EPSF);
        float gam = 1.f / sqrtf(gsq);
        gam = fminf(fmaxf(gam, 1.f + EPSF), 1e16f);
        myw = __expf(s - smax) * gam;
        kf = th / rr;
        red[tid] = myw;
    }
    __syncthreads();
    for (int o = 64; o; o >>= 1) {
        if (tid < o) red[tid] += red[tid + o];
        __syncthreads();
    }
    const float wsum = red[0];
    if (tid < 128) wk[tid] = (myw / wsum) * kf;
    __syncthreads();

    float acc = 0.f;
    if (tid < 128) {
        for (int t = 0; t < TT; t++)
            acc += wk[t] * g_ys_f[((ll)t * BB + b) * HH + tid];
    } else {
        const int k = tid - 128;
        for (int t = 0; t < TT; t++)
            acc += wk[t] * g_ys_b[((ll)(TT - 1 - t) * BB + b) * HH + k];
    }
    out[b * DD + tid] = acc;

    float* hout = out + BB * DD;
    if (tid < 128) {
        hout[b * HH + tid] = g_ys_f[((ll)(TT - 1) * BB + b) * HH + tid];
    } else {
        const int k = tid - 128;
        hout[BB * HH + b * HH + k] = g_ys_b[((ll)(TT - 1) * BB + b) * HH + k];
    }
}

// ============================================================
extern "C" void kernel_launch(void* const* d_in, const int* in_sizes, int n_in,
                              void* d_out, int out_size)
{
    const int*   tokens = (const int*)d_in[0];
    const float* hidden = (const float*)d_in[1];
    const float* emb    = (const float*)d_in[2];
    const float* W_ih_f = (const float*)d_in[3];
    const float* W_hh_f = (const float*)d_in[4];
    const float* b_ih_f = (const float*)d_in[5];
    const float* b_hh_f = (const float*)d_in[6];
    const float* W_ih_b = (const float*)d_in[7];
    const float* W_hh_b = (const float*)d_in[8];
    const float* b_ih_b = (const float*)d_in[9];
    const float* b_hh_b = (const float*)d_in[10];
    const float* attn2W = (const float*)d_in[11];
    const float* attn2b = (const float*)d_in[12];
    const float* cent   = (const float*)d_in[13];
    const float* beta   = (const float*)d_in[14];
    float* out = (float*)d_out;

    cudaFuncSetAttribute(k1_mma, cudaFuncAttributeMaxDynamicSharedMemorySize, MMA_SMEM);
    cudaFuncSetAttribute(k3_mma, cudaFuncAttributeMaxDynamicSharedMemorySize, MMA_SMEM);

    // launch order chosen so k2_scan lands in the ncu capture slot (4th)
    k0_cent<<<1, 32>>>(cent);
    k1_mma<<<dim3(6, 256), 256, MMA_SMEM>>>(tokens, emb, W_ih_f, b_ih_f, W_ih_b, b_ih_b, 0);
    k1_mma<<<dim3(6, 256), 256, MMA_SMEM>>>(tokens, emb, W_ih_f, b_ih_f, W_ih_b, b_ih_b, 256);
    k2_scan<<<128, 384>>>(hidden, W_hh_f, b_hh_f, W_hh_b, b_hh_b);
    k3_mma<<<dim3(2, 512), 256, MMA_SMEM>>>(attn2W, attn2b);
    k34_scores<<<8192, 256>>>(cent, beta);
    k5_pool<<<512, 256>>>(out);
}

// round 8
// speedup vs baseline: 1.6428x; 1.6428x over previous
#include <cuda_runtime.h>
#include <math.h>

#define TT   128
#define BB   512
#define HH   128
#define EMBD 300
#define DD   256
#define G3   384
#define EPSF 1e-7f

typedef long long ll;

__device__ float g_xp_f[TT * BB * G3];
__device__ float g_xp_b[TT * BB * G3];
__device__ float g_ys_f[TT * BB * HH];
__device__ float g_ys_b[TT * BB * HH];
__device__ float g_hyp[TT * BB * DD];
__device__ float g_scores[TT * BB];
__device__ float g_rr2[TT * BB];
__device__ float g_cc[2];   // [cosh(rc), sinh(rc)/rc]

// ---- tf32 helpers ----
__device__ __forceinline__ unsigned f2tf32(float v) {
    unsigned u;
    asm("cvt.rna.tf32.f32 %0, %1;" : "=r"(u) : "f"(v));
    return u;
}
__device__ __forceinline__ void mma_tf32(float* c, const unsigned* a, const unsigned* b) {
    asm volatile(
        "mma.sync.aligned.m16n8k8.row.col.f32.tf32.tf32.f32 "
        "{%0,%1,%2,%3}, {%4,%5,%6,%7}, {%8,%9}, {%0,%1,%2,%3};"
        : "+f"(c[0]), "+f"(c[1]), "+f"(c[2]), "+f"(c[3])
        : "r"(a[0]), "r"(a[1]), "r"(a[2]), "r"(a[3]), "r"(b[0]), "r"(b[1]));
}

#define ACH 1032
#define BCH 1032
#define MMA_SMEM ((8 * ACH + 8 * BCH) * 4)   // 66,048 B

__device__ __forceinline__ int a_off(int r, int kk) {
    return (kk >> 3) * ACH + (r >> 4) * 128 + ((((r & 7) << 2) | (kk & 3)) << 2)
           + ((r >> 3) & 1) + (((kk >> 2) & 1) << 1);
}
__device__ __forceinline__ int b_off(int c, int kk) {
    return (kk >> 3) * BCH + (c >> 3) * 64 + ((((c & 7) << 2) | (kk & 3)) << 1)
           + ((kk >> 2) & 1);
}

// ============================================================
// K0: centroid constants (1 block, 32 threads) — idempotent
// ============================================================
__global__ void k0_cent(const float* __restrict__ cent)
{
    const int lane = threadIdx.x;
    float c2 = 0.f;
    #pragma unroll
    for (int i = 0; i < 8; i++) {
        const float cv = cent[lane + 32 * i];
        c2 += cv * cv;
    }
    #pragma unroll
    for (int o = 16; o; o >>= 1) c2 += __shfl_xor_sync(0xffffffffu, c2, o);
    if (lane == 0) {
        const float rc = sqrtf(c2);
        g_cc[0] = coshf(rc);
        g_cc[1] = sinhf(rc) / rc;
    }
}

// ============================================================
// K1: embed gather + input projections via tf32 mma.
// grid (6 colblocks, 512 rowblocks). Staging: lanes along k
// (LDG.128 coalesced), 4x STS.32 into fragment layout.
// ============================================================
__global__ __launch_bounds__(256) void k1_mma(
    const int* __restrict__ tokens, const float* __restrict__ emb,
    const float* __restrict__ Wf, const float* __restrict__ bfv,
    const float* __restrict__ Wb, const float* __restrict__ bbv)
{
    extern __shared__ unsigned sm_u[];
    unsigned* As = sm_u;
    unsigned* Bs = sm_u + 8 * ACH;
    __shared__ int tk[128];

    const int tid  = threadIdx.x;
    const int lane = tid & 31;
    const int w    = tid >> 5;
    const int wm   = w >> 2;
    const int wn   = w & 3;
    const int row0 = blockIdx.y * 128;
    const int t    = row0 >> 9;
    const int b0   = row0 & 511;
    const int coff = blockIdx.x * 128;

    if (tid < 128) tk[tid] = tokens[row0 + tid];

    const bool fwd = (coff < G3);
    const float* Wsrc = fwd ? Wf : Wb;
    const float* bsrc = fwd ? bfv : bbv;
    const int cbase = fwd ? coff : (coff - G3);

    float acc[4][4][4];
    #pragma unroll
    for (int i = 0; i < 4; i++)
        #pragma unroll
        for (int j = 0; j < 4; j++)
            #pragma unroll
            for (int q = 0; q < 4; q++) acc[i][j][q] = 0.f;

    const int fl = tid & 15;       // float4 index along k slice
    const int rr = tid >> 4;       // 16 rows per pass

    for (int ks = 0; ks < 5; ks++) {
        const int kg4 = ks * 64 + fl * 4;
        const bool kv = (kg4 < EMBD);   // EMBD % 4 == 0 -> all-or-nothing
        __syncthreads();
        // stage A: one LDG.128 per row-chunk (coalesced along k)
        #pragma unroll
        for (int rp = 0; rp < 8; rp++) {
            const int r = rp * 16 + rr;
            float4 v = make_float4(0.f, 0.f, 0.f, 0.f);
            if (kv) v = *(const float4*)(emb + (ll)tk[r] * EMBD + kg4);
            As[a_off(r, fl * 4 + 0)] = f2tf32(v.x);
            As[a_off(r, fl * 4 + 1)] = f2tf32(v.y);
            As[a_off(r, fl * 4 + 2)] = f2tf32(v.z);
            As[a_off(r, fl * 4 + 3)] = f2tf32(v.w);
        }
        // stage B: coalesced along k
        #pragma unroll
        for (int cp = 0; cp < 8; cp++) {
            const int c = cp * 16 + rr;
            float4 v = make_float4(0.f, 0.f, 0.f, 0.f);
            if (kv) v = *(const float4*)(Wsrc + (ll)(cbase + c) * EMBD + kg4);
            Bs[b_off(c, fl * 4 + 0)] = f2tf32(v.x);
            Bs[b_off(c, fl * 4 + 1)] = f2tf32(v.y);
            Bs[b_off(c, fl * 4 + 2)] = f2tf32(v.z);
            Bs[b_off(c, fl * 4 + 3)] = f2tf32(v.w);
        }
        __syncthreads();
        #pragma unroll
        for (int ck = 0; ck < 8; ck++) {
            unsigned a[4][4], b[4][2];
            #pragma unroll
            for (int i = 0; i < 4; i++) {
                uint4 av = *(const uint4*)(As + ck * ACH + (wm * 4 + i) * 128 + lane * 4);
                a[i][0] = av.x; a[i][1] = av.y; a[i][2] = av.z; a[i][3] = av.w;
            }
            #pragma unroll
            for (int j = 0; j < 4; j++) {
                uint2 bv = *(const uint2*)(Bs + ck * BCH + (wn * 4 + j) * 64 + lane * 2);
                b[j][0] = bv.x; b[j][1] = bv.y;
            }
            #pragma unroll
            for (int i = 0; i < 4; i++)
                #pragma unroll
                for (int j = 0; j < 4; j++)
                    mma_tf32(acc[i][j], a[i], b[j]);
        }
    }

    const int tb = TT - 1 - t;
    #pragma unroll
    for (int j = 0; j < 4; j++) {
        const int cl = cbase + wn * 32 + j * 8 + 2 * (lane & 3);
        const float bv0 = bsrc[cl], bv1 = bsrc[cl + 1];
        #pragma unroll
        for (int i = 0; i < 4; i++) {
            const int b_lo = b0 + wm * 64 + i * 16 + (lane >> 2);
            float2 vlo = make_float2(acc[i][j][0] + bv0, acc[i][j][1] + bv1);
            float2 vhi = make_float2(acc[i][j][2] + bv0, acc[i][j][3] + bv1);
            if (fwd) {
                *(float2*)&g_xp_f[((ll)t * BB + b_lo) * G3 + cl] = vlo;
                *(float2*)&g_xp_f[((ll)t * BB + b_lo + 8) * G3 + cl] = vhi;
            } else {
                *(float2*)&g_xp_b[((ll)tb * BB + b_lo) * G3 + cl] = vlo;
                *(float2*)&g_xp_b[((ll)tb * BB + b_lo + 8) * G3 + cl] = vhi;
            }
        }
    }
}

// ============================================================
// K2: GRU scan (fp32). 128 blocks x 384 thr. (unchanged)
// ============================================================
__global__ __launch_bounds__(384, 1) void k2_scan(
    const float* __restrict__ hidden,
    const float* __restrict__ Whh_f, const float* __restrict__ bhh_f,
    const float* __restrict__ Whh_b, const float* __restrict__ bhh_b)
{
    __shared__ __align__(16) float hs[8 * 128];
    __shared__ float sg[256 * 9];

    const int tid = threadIdx.x;
    const int dir = blockIdx.x >> 6;
    const int b0  = (blockIdx.x & 63) * 8;

    const float* Whh = dir ? Whh_b : Whh_f;
    const float* bhh = dir ? bhh_b : bhh_f;
    const float* xp  = dir ? g_xp_b : g_xp_f;
    float* ys        = dir ? g_ys_b : g_ys_f;

    float4 w[32];
    #pragma unroll
    for (int i = 0; i < 32; i++)
        w[i] = *(const float4*)&Whh[tid * 128 + i * 4];
    const float bj = bhh[tid];

    if (tid < 128) {
        #pragma unroll
        for (int r = 0; r < 8; r++)
            hs[r * 128 + tid] = hidden[((ll)dir * BB + b0 + r) * HH + tid];
    }
    __syncthreads();

    const float4* h4 = (const float4*)hs;

    for (int t = 0; t < TT; t++) {
        float xpv[8];
        const float* xpt = xp + ((ll)t * BB + b0) * G3 + tid;
        #pragma unroll
        for (int r = 0; r < 8; r++) xpv[r] = xpt[r * (ll)G3];

        float acc[8];
        #pragma unroll
        for (int r = 0; r < 8; r++) acc[r] = 0.f;

        #pragma unroll
        for (int i = 0; i < 32; i++) {
            const float4 wi = w[i];
            #pragma unroll
            for (int r = 0; r < 8; r++) {
                const float4 hv = h4[r * 32 + i];
                acc[r] += wi.x * hv.x + wi.y * hv.y + wi.z * hv.z + wi.w * hv.w;
            }
        }

        if (tid < 256) {
            #pragma unroll
            for (int r = 0; r < 8; r++) {
                const float x = xpv[r] + acc[r] + bj;
                sg[tid * 9 + r] = __fdividef(1.f, 1.f + __expf(-x));
            }
        }
        __syncthreads();
        if (tid >= 256) {
            const int k = tid - 256;
            float* ysrow = ys + ((ll)t * BB + b0) * HH + k;
            #pragma unroll
            for (int r = 0; r < 8; r++) {
                const float rg = sg[k * 9 + r];
                const float zg = sg[(128 + k) * 9 + r];
                const float a  = xpv[r] + rg * (acc[r] + bj);
                const float e  = __expf(2.f * a);
                const float n  = 1.f - __fdividef(2.f, e + 1.f);
                const float ho = hs[r * 128 + k];
                const float hnew = (1.f - zg) * n + zg * ho;
                hs[r * 128 + k] = hnew;
                ysrow[r * (ll)HH] = hnew;
            }
        }
        __syncthreads();
    }
}

// ============================================================
// K3: hyp = tanh(f @ attn2_W^T + b) via tf32 mma.
// grid (2, 512); staging lanes along k (coalesced).
// ============================================================
__global__ __launch_bounds__(256) void k3_mma(
    const float* __restrict__ W, const float* __restrict__ bias)
{
    extern __shared__ unsigned sm_u[];
    unsigned* As = sm_u;
    unsigned* Bs = sm_u + 8 * ACH;

    const int tid  = threadIdx.x;
    const int lane = tid & 31;
    const int w    = tid >> 5;
    const int wm   = w >> 2;
    const int wn   = w & 3;
    const int row0 = blockIdx.y * 128;
    const int t    = row0 >> 9;
    const int b0   = row0 & 511;
    const int tb   = TT - 1 - t;
    const int coff = blockIdx.x * 128;

    float acc[4][4][4];
    #pragma unroll
    for (int i = 0; i < 4; i++)
        #pragma unroll
        for (int j = 0; j < 4; j++)
            #pragma unroll
            for (int q = 0; q < 4; q++) acc[i][j][q] = 0.f;

    const int fl = tid & 15;
    const int rr = tid >> 4;

    for (int ks = 0; ks < 4; ks++) {
        const int kg4 = ks * 64 + fl * 4;
        __syncthreads();
        // stage A from ys_f (ks<2) or ys_b (ks>=2), coalesced along k
        const float* ysrc = (ks < 2) ? (g_ys_f + (ll)t * BB * HH)
                                     : (g_ys_b + (ll)tb * BB * HH);
        const int kk4 = (ks < 2) ? kg4 : (kg4 - HH);
        #pragma unroll
        for (int rp = 0; rp < 8; rp++) {
            const int r = rp * 16 + rr;
            float4 v = *(const float4*)(ysrc + (ll)(b0 + r) * HH + kk4);
            As[a_off(r, fl * 4 + 0)] = f2tf32(v.x);
            As[a_off(r, fl * 4 + 1)] = f2tf32(v.y);
            As[a_off(r, fl * 4 + 2)] = f2tf32(v.z);
            As[a_off(r, fl * 4 + 3)] = f2tf32(v.w);
        }
        #pragma unroll
        for (int cp = 0; cp < 8; cp++) {
            const int c = cp * 16 + rr;
            float4 v = *(const float4*)(W + (ll)(coff + c) * DD + kg4);
            Bs[b_off(c, fl * 4 + 0)] = f2tf32(v.x);
            Bs[b_off(c, fl * 4 + 1)] = f2tf32(v.y);
            Bs[b_off(c, fl * 4 + 2)] = f2tf32(v.z);
            Bs[b_off(c, fl * 4 + 3)] = f2tf32(v.w);
        }
        __syncthreads();
        #pragma unroll
        for (int ck = 0; ck < 8; ck++) {
            unsigned a[4][4], b[4][2];
            #pragma unroll
            for (int i = 0; i < 4; i++) {
                uint4 av = *(const uint4*)(As + ck * ACH + (wm * 4 + i) * 128 + lane * 4);
                a[i][0] = av.x; a[i][1] = av.y; a[i][2] = av.z; a[i][3] = av.w;
            }
            #pragma unroll
            for (int j = 0; j < 4; j++) {
                uint2 bv = *(const uint2*)(Bs + ck * BCH + (wn * 4 + j) * 64 + lane * 2);
                b[j][0] = bv.x; b[j][1] = bv.y;
            }
            #pragma unroll
            for (int i = 0; i < 4; i++)
                #pragma unroll
                for (int j = 0; j < 4; j++)
                    mma_tf32(acc[i][j], a[i], b[j]);
        }
    }

    #pragma unroll
    for (int j = 0; j < 4; j++) {
        const int n = coff + wn * 32 + j * 8 + 2 * (lane & 3);
        const float bv0 = bias[n], bv1 = bias[n + 1];
        #pragma unroll
        for (int i = 0; i < 4; i++) {
            const int m_lo = row0 + wm * 64 + i * 16 + (lane >> 2);
            float v[4] = {acc[i][j][0] + bv0, acc[i][j][1] + bv1,
                          acc[i][j][2] + bv0, acc[i][j][3] + bv1};
            #pragma unroll
            for (int q = 0; q < 4; q++) {
                const float e = __expf(2.f * v[q]);
                v[q] = 1.f - __fdividef(2.f, e + 1.f);
            }
            *(float2*)&g_hyp[(ll)m_lo * DD + n] = make_float2(v[0], v[1]);
            *(float2*)&g_hyp[(ll)(m_lo + 8) * DD + n] = make_float2(v[2], v[3]);
        }
    }
}

// ============================================================
// K34: fused ||f||^2 + hyperbolic score, one warp per (t,b) row
// ============================================================
__global__ __launch_bounds__(256) void k34_scores(
    const float* __restrict__ cent, const float* __restrict__ beta)
{
    const int row  = blockIdx.x * 8 + (threadIdx.x >> 5);
    const int lane = threadIdx.x & 31;
    const int t = row >> 9, b = row & 511;
    const float* yf = g_ys_f + ((ll)t * BB + b) * HH;
    const float* yb = g_ys_b + ((ll)(TT - 1 - t) * BB + b) * HH;
    const float* hy = g_hyp + (ll)row * DD;

    float s = 0.f, h2 = 0.f, cd = 0.f;
    #pragma unroll
    for (int i = 0; i < 4; i++) {
        const float a = yf[lane + 32 * i];
        const float c = yb[lane + 32 * i];
        s += a * a + c * c;
    }
    #pragma unroll
    for (int i = 0; i < 8; i++) {
        const float hv = hy[lane + 32 * i];
        const float cv = cent[lane + 32 * i];
        h2 += hv * hv; cd += hv * cv;
    }
    #pragma unroll
    for (int o = 16; o; o >>= 1) {
        s  += __shfl_xor_sync(0xffffffffu, s, o);
        h2 += __shfl_xor_sync(0xffffffffu, h2, o);
        cd += __shfl_xor_sync(0xffffffffu, cd, o);
    }
    if (lane == 0) {
        g_rr2[row] = s;
        const float rh = sqrtf(h2);
        float pm = coshf(rh) * g_cc[0] - (sinhf(rh) / rh) * g_cc[1] * cd;
        pm = fminf(fmaxf(pm, 1.f + EPSF), 1e16f);
        const float dist = logf(pm) + log1pf(sqrtf(pm * pm - 1.f + EPSF) / pm);
        g_scores[row] = -beta[0] * dist - 1.f;
    }
}

// ============================================================
// K5: softmax x gamma Einstein-midpoint pooling + h_output
// ============================================================
__global__ __launch_bounds__(256) void k5_pool(float* __restrict__ out)
{
    __shared__ float wk[128];
    __shared__ float red[128];
    const int b = blockIdx.x, tid = threadIdx.x;

    float s = -1e30f;
    if (tid < 128) {
        s = g_scores[tid * BB + b];
        red[tid] = s;
    }
    __syncthreads();
    for (int o = 64; o; o >>= 1) {
        if (tid < o) red[tid] = fmaxf(red[tid], red[tid + o]);
        __syncthreads();
    }
    const float smax = red[0];
    __syncthreads();

    float myw = 0.f, kf = 0.f;
    if (tid < 128) {
        const float rr = sqrtf(g_rr2[tid * BB + b]);
        const float sh = sinhf(rr), ch = coshf(rr);
        const float th = sh / ch;
        float gsq = 1.f - th * th;
        gsq = fminf(fmaxf(gsq, EPSF), 1.f - EPSF);
        float gam = 1.f / sqrtf(gsq);
        gam = fminf(fmaxf(gam, 1.f + EPSF), 1e16f);
        myw = __expf(s - smax) * gam;
        kf = th / rr;
        red[tid] = myw;
    }
    __syncthreads();
    for (int o = 64; o; o >>= 1) {
        if (tid < o) red[tid] += red[tid + o];
        __syncthreads();
    }
    const float wsum = red[0];
    if (tid < 128) wk[tid] = (myw / wsum) * kf;
    __syncthreads();

    float acc = 0.f;
    if (tid < 128) {
        for (int t = 0; t < TT; t++)
            acc += wk[t] * g_ys_f[((ll)t * BB + b) * HH + tid];
    } else {
        const int k = tid - 128;
        for (int t = 0; t < TT; t++)
            acc += wk[t] * g_ys_b[((ll)(TT - 1 - t) * BB + b) * HH + k];
    }
    out[b * DD + tid] = acc;

    float* hout = out + BB * DD;
    if (tid < 128) {
        hout[b * HH + tid] = g_ys_f[((ll)(TT - 1) * BB + b) * HH + tid];
    } else {
        const int k = tid - 128;
        hout[BB * HH + b * HH + k] = g_ys_b[((ll)(TT - 1) * BB + b) * HH + k];
    }
}

// ============================================================
extern "C" void kernel_launch(void* const* d_in, const int* in_sizes, int n_in,
                              void* d_out, int out_size)
{
    const int*   tokens = (const int*)d_in[0];
    const float* hidden = (const float*)d_in[1];
    const float* emb    = (const float*)d_in[2];
    const float* W_ih_f = (const float*)d_in[3];
    const float* W_hh_f = (const float*)d_in[4];
    const float* b_ih_f = (const float*)d_in[5];
    const float* b_hh_f = (const float*)d_in[6];
    const float* W_ih_b = (const float*)d_in[7];
    const float* W_hh_b = (const float*)d_in[8];
    const float* b_ih_b = (const float*)d_in[9];
    const float* b_hh_b = (const float*)d_in[10];
    const float* attn2W = (const float*)d_in[11];
    const float* attn2b = (const float*)d_in[12];
    const float* cent   = (const float*)d_in[13];
    const float* beta   = (const float*)d_in[14];
    float* out = (float*)d_out;

    cudaFuncSetAttribute(k1_mma, cudaFuncAttributeMaxDynamicSharedMemorySize, MMA_SMEM);
    cudaFuncSetAttribute(k3_mma, cudaFuncAttributeMaxDynamicSharedMemorySize, MMA_SMEM);

    // k0 launched 3x (idempotent) so the ncu capture slot (4th launch) = k1_mma
    k0_cent<<<1, 32>>>(cent);
    k0_cent<<<1, 32>>>(cent);
    k0_cent<<<1, 32>>>(cent);
    k1_mma<<<dim3(6, 512), 256, MMA_SMEM>>>(tokens, emb, W_ih_f, b_ih_f, W_ih_b, b_ih_b);
    k2_scan<<<128, 384>>>(hidden, W_hh_f, b_hh_f, W_hh_b, b_hh_b);
    k3_mma<<<dim3(2, 512), 256, MMA_SMEM>>>(attn2W, attn2b);
    k34_scores<<<8192, 256>>>(cent, beta);
    k5_pool<<<512, 256>>>(out);
}